// round 14
// baseline (speedup 1.0000x reference)
#include <cuda_runtime.h>
#include <cstdint>

#define BSZ    64
#define BEAM   8
#define VOCAB  50257
#define KTOP   16
#define ROWS   (BSZ * BEAM)
#define THREADS 256
#define NWARP  (THREADS / 32)
#define CAP    4608               // >= 256 guard carry + 4096 appends/pair + slack
#define GHI    256                // pass-0 overflow guard
#define FHI    160                // fallback compaction trigger
#define NEG_INF __int_as_float(0xff800000)

typedef unsigned long long u64;

// Inter-CTA scratch (allocation-free)
__device__ float g_s1val[ROWS][KTOP];
__device__ int   g_s1idx[ROWS][KTOP];
__device__ int   g_arrive[BSZ];   // zero-init; finisher resets -> graph-replay safe

__device__ __forceinline__ unsigned ford(float f) {
    unsigned u = __float_as_uint(f);
    return u ^ ((unsigned)((int)u >> 31) | 0x80000000u);
}
__device__ __forceinline__ float funord(unsigned u) {
    return __uint_as_float((u & 0x80000000u) ? (u ^ 0x80000000u) : ~u);
}
__device__ __forceinline__ u64 umax64(u64 a, u64 b) { return a > b ? a : b; }
__device__ __forceinline__ float vloadf(const float* p) { return *(const volatile float*)p; }
__device__ __forceinline__ int   vloadi(const int*   p) { return *(const volatile int*)p; }

// Exact block top-16 of THREADS candidates in loc (0 = empty, nonzero keys
// unique). Winners descending in win[0..15]. All threads must call.
__device__ __forceinline__ void block_topk16_1(u64 loc0, u64* win, u64* wtmp,
                                               int tid, int lane, int wid) {
    u64 loc = loc0;
    for (int r = 0; r < KTOP; ++r) {
        u64 lm = loc;
        u64 wm = lm;
#pragma unroll
        for (int off = 16; off; off >>= 1)
            wm = umax64(wm, __shfl_down_sync(0xffffffffu, wm, off));
        wm = __shfl_sync(0xffffffffu, wm, 0);
        if (lane == 0) wtmp[wid * KTOP + r] = wm;
        if (lm == wm && wm) loc = 0ull;
    }
    __syncthreads();
    if (wid == 0) {
        u64 m[4];                 // 8 warps * 16 = 128 keys, 4 per lane
#pragma unroll
        for (int s = 0; s < 4; ++s) m[s] = wtmp[lane + s * 32];
        for (int r = 0; r < KTOP; ++r) {
            u64 lm = umax64(umax64(m[0], m[1]), umax64(m[2], m[3]));
            u64 wm = lm;
#pragma unroll
            for (int off = 16; off; off >>= 1)
                wm = umax64(wm, __shfl_down_sync(0xffffffffu, wm, off));
            wm = __shfl_sync(0xffffffffu, wm, 0);
            if (lane == 0) win[r] = wm;
            if (lm == wm && wm) {
#pragma unroll
                for (int s = 0; s < 4; ++s) if (m[s] == wm) m[s] = 0ull;
            }
        }
    }
    __syncthreads();
}

// Rare big-buffer selection: smem-scan (low register footprint by design —
// this path statistically never executes; it only must not inflate the
// kernel's register allocation). Zeroes winners inside buf.
__device__ __noinline__ void topk16_scan(u64* buf, int C, u64* win, u64* wtmp,
                                         int tid, int lane, int wid) {
    for (int r = 0; r < KTOP; ++r) {
        u64 lm = 0ull;
        for (int e = tid; e < C; e += THREADS) lm = umax64(lm, buf[e]);
#pragma unroll
        for (int off = 16; off; off >>= 1)
            lm = umax64(lm, __shfl_down_sync(0xffffffffu, lm, off));
        if (lane == 0) wtmp[wid] = lm;
        __syncthreads();
        if (tid == 0) {
            u64 w = wtmp[0];
#pragma unroll
            for (int s = 1; s < NWARP; ++s) w = umax64(w, wtmp[s]);
            win[r] = w;
        }
        __syncthreads();
        u64 w = win[r];
        for (int e = tid; e < C; e += THREADS)
            if (buf[e] == w) buf[e] = 0ull;    // unique keys -> one owner
        __syncthreads();
    }
}

__global__ __launch_bounds__(THREADS)
void dss_kernel(const float* __restrict__ lprobs,
                const float* __restrict__ scores,
                const int* __restrict__ stepp, int sdim,
                float* __restrict__ out) {
    __shared__ u64 buf[CAP];
    __shared__ u64 win[KTOP];
    __shared__ u64 wtmp[NWARP * KTOP];
    __shared__ int cnt;
    __shared__ int lastflag;

    const int r    = blockIdx.x;
    const int b    = r / BEAM;
    const int tid  = threadIdx.x;
    const int lane = tid & 31;
    const int wid  = tid >> 5;

    int step = *stepp;
    if (step < 0 || step > sdim) step = sdim;
    const float add = (step > 0) ? scores[r * sdim + (step - 1)] : 0.0f;

    if (tid == 0) cnt = 0;

    const float* base = lprobs + (size_t)r * VOCAB;
    const uintptr_t addr = (uintptr_t)base;
    const int pre  = (int)(((16u - (unsigned)(addr & 15u)) & 15u) >> 2);  // 0..3
    const int NV4  = (VOCAB - pre) >> 2;
    const int tail = VOCAB - pre - (NV4 << 2);
    const float4* b4 = (const float4*)(base + pre);

    const int NITER = (NV4 + 2 * THREADS - 1) / (2 * THREADS);   // 25
    const int NFULL = NV4 >> 9;                                  // 24 full iters

    float T;
    float4 A0, A1, B0, B1;
    const float4 FILL = make_float4(NEG_INF, NEG_INF, NEG_INF, NEG_INF);

#define LD2(IT, R0, R1) do {                                   \
        int _i0 = (IT) * 2 * THREADS + tid;                    \
        int _i1 = _i0 + THREADS;                               \
        R0 = (_i0 < NV4) ? __ldcs(b4 + _i0) : FILL;            \
        R1 = (_i1 < NV4) ? __ldcs(b4 + _i1) : FILL;            \
    } while (0)

#define LD2U(IT, R0, R1) do {                                  \
        int _i0 = (IT) * 2 * THREADS + tid;                    \
        R0 = __ldcs(b4 + _i0);                                 \
        R1 = __ldcs(b4 + _i0 + THREADS);                       \
    } while (0)

    // gate on raw max + single add (fp add monotone: max(x)+add == max(x+add));
    // slow path: per-element predicated atomic append (order-independent merge).
#define PROC(IT, R0, R1) do {                                                 \
        float m8 = fmaxf(fmaxf(fmaxf(R0.x, R0.y), fmaxf(R0.z, R0.w)),         \
                         fmaxf(fmaxf(R1.x, R1.y), fmaxf(R1.z, R1.w)));        \
        if (__any_sync(0xffffffffu, m8 + add >= T)) {                         \
            const int _i0 = (IT) * 2 * THREADS + tid;                         \
            float vv[8] = {R0.x + add, R0.y + add, R0.z + add, R0.w + add,    \
                           R1.x + add, R1.y + add, R1.z + add, R1.w + add};   \
            _Pragma("unroll")                                                 \
            for (int j = 0; j < 8; ++j) {                                     \
                if (vv[j] >= T) {                                             \
                    int p = atomicAdd(&cnt, 1);                               \
                    unsigned gidx = (unsigned)(pre +                          \
                        (_i0 + (j >> 2) * THREADS) * 4 + (j & 3));            \
                    buf[p] = ((u64)ford(vv[j]) << 32) | (unsigned)~gidx;      \
                }                                                             \
            }                                                                 \
        }                                                                     \
    } while (0)

#define PROLOGUE() do {                                                       \
        if (tid < pre) {                                                      \
            float v = base[tid] + add;                                        \
            if (v >= T) {                                                     \
                int p = atomicAdd(&cnt, 1);                                   \
                buf[p] = ((u64)ford(v) << 32) | (unsigned)~((unsigned)tid);   \
            }                                                                 \
        }                                                                     \
        int t2 = tid - 64;                                                    \
        if (t2 >= 0 && t2 < tail) {                                           \
            int gib = pre + (NV4 << 2) + t2;                                  \
            float v = base[gib] + add;                                        \
            if (v >= T) {                                                     \
                int p = atomicAdd(&cnt, 1);                                   \
                buf[p] = ((u64)ford(v) << 32) | (unsigned)~((unsigned)gib);   \
            }                                                                 \
        }                                                                     \
    } while (0)

    // Compaction: read-sync-branch (uniform, no divergent-barrier race).
#define COMPACT_IF(THRESH) do {                                               \
        __syncthreads();                                                      \
        int _Cg = cnt;                                                        \
        __syncthreads();                                                      \
        if (_Cg > (THRESH)) {                                                 \
            topk16_scan(buf, _Cg, win, wtmp, tid, lane, wid);                 \
            if (tid < KTOP) buf[tid] = win[tid];                              \
            if (tid == 0) cnt = KTOP;                                         \
            T = funord((unsigned)(win[KTOP - 1] >> 32));                      \
            __syncthreads();                                                  \
        }                                                                     \
    } while (0)

    // ---------- PASS 0: fixed statistical threshold, exact via guards ----------
    LD2U(0, A0, A1);
    LD2U(1, B0, B1);
    T = add + 3.1f;          // P(N(0,1) >= 3.1) ~ 9.7e-4 -> ~49 survivors expected
    __syncthreads();         // cnt = 0 visible
    PROLOGUE();

    int it = 0;
    for (; it + 3 < NFULL; it += 2) {        // loads it+2, it+3 all in-bounds
        PROC(it, A0, A1);
        LD2U(it + 2, A0, A1);
        PROC(it + 1, B0, B1);
        LD2U(it + 3, B0, B1);
        COMPACT_IF(GHI);                     // overflow guard (never fires statistically)
    }
    // it == NFULL-2: process NFULL-2, NFULL-1; last (partial) iteration predicated
    PROC(it, A0, A1);
    LD2(NFULL, A0, A1);
    PROC(it + 1, B0, B1);
    COMPACT_IF(GHI);
    if (NFULL < NITER) PROC(NFULL, A0, A1);

    __syncthreads();
    int Cend = cnt;
    __syncthreads();

    // ---------- FALLBACK (adversarial only): exact seed + compaction loop ------
    if (Cend < KTOP) {
        if (tid == 0) cnt = 0;
        LD2(0, A0, A1);
        {   // seed T = 16th of 256 per-thread maxima -> guarantees >=16 survivors
            float mx = fmaxf(fmaxf(fmaxf(A0.x, A0.y), fmaxf(A0.z, A0.w)),
                             fmaxf(fmaxf(A1.x, A1.y), fmaxf(A1.z, A1.w))) + add;
            block_topk16_1(((u64)ford(mx) << 32) | (unsigned)~((unsigned)tid),
                           win, wtmp, tid, lane, wid);   // also syncs cnt=0
            T = funord((unsigned)(win[KTOP - 1] >> 32));
        }
        PROLOGUE();
        for (int j2 = 0; j2 < NITER; ++j2) {
            LD2(j2, A0, A1);
            PROC(j2, A0, A1);
            COMPACT_IF(FHI);
        }
        __syncthreads();
        Cend = cnt;
        __syncthreads();
    }

    // ---------- final exact selection for this row ----------
    if (Cend <= THREADS) {
        block_topk16_1((tid < Cend) ? buf[tid] : 0ull, win, wtmp, tid, lane, wid);
    } else {
        topk16_scan(buf, Cend, win, wtmp, tid, lane, wid);
    }

    if (tid < KTOP) {
        u64 w = win[tid];
        g_s1val[r][tid] = funord((unsigned)(w >> 32));
        g_s1idx[r][tid] = (int)~((unsigned)w);
    }
    __threadfence();
    __syncthreads();

    // last CTA per batch runs the final 128 -> 16 selection
    if (tid == 0) lastflag = (atomicAdd(&g_arrive[b], 1) == BEAM - 1) ? 1 : 0;
    __syncthreads();
    if (!lastflag) return;
    __threadfence();   // acquire: see all beams' g_s1 writes

    float* out_scores = out;
    float* out_idx    = out + BSZ * KTOP;
    float* out_beam   = out + 2 * BSZ * KTOP;

    if (step == 0) {
        if (tid < KTOP) {
            out_scores[b * KTOP + tid] = vloadf(&g_s1val[b * BEAM][tid]);
            out_idx[b * KTOP + tid]    = (float)vloadi(&g_s1idx[b * BEAM][tid]);
            out_beam[b * KTOP + tid]   = 0.0f;
        }
        if (tid == 0) g_arrive[b] = 0;
        return;
    }

    {
        u64 k = 0ull;
        if (tid < BEAM * KTOP) {
            const int beam = tid >> 4, pos = tid & 15;
            const float v = vloadf(&g_s1val[b * BEAM + beam][pos])
                            - (float)(pos + 1) * 0.5f;
            k = ((u64)ford(v) << 32) | (unsigned)~((unsigned)tid);
        }
        block_topk16_1(k, win, wtmp, tid, lane, wid);
    }
    if (tid < KTOP) {
        u64 w = win[tid];
        const int j = (int)~((unsigned)w);       // flat candidate == reference fi
        const int beam = j >> 4, pos = j & 15;
        out_scores[b * KTOP + tid] = funord((unsigned)(w >> 32));
        out_idx[b * KTOP + tid]    = (float)vloadi(&g_s1idx[b * BEAM + beam][pos]);
        out_beam[b * KTOP + tid]   = (float)beam;
    }
    if (tid == 0) g_arrive[b] = 0;
}

extern "C" void kernel_launch(void* const* d_in, const int* in_sizes, int n_in,
                              void* d_out, int out_size) {
    const float* lprobs = (const float*)d_in[0];
    const float* scores = (const float*)d_in[1];
    const int*   stepp  = (const int*)d_in[2];
    const int sdim = in_sizes[1] / ROWS;

    dss_kernel<<<ROWS, THREADS>>>(lprobs, scores, stepp, sdim, (float*)d_out);
}

// round 15
// speedup vs baseline: 1.3724x; 1.3724x over previous
#include <cuda_runtime.h>
#include <cstdint>

#define BSZ    64
#define BEAM   8
#define VOCAB  50257
#define KTOP   16
#define ROWS   (BSZ * BEAM)
#define THREADS 256
#define NWARP  (THREADS / 32)
#define CAP    4608
#define FHI    160                // fallback compaction trigger
#define NEG_INF __int_as_float(0xff800000)

typedef unsigned long long u64;

// Inter-CTA scratch (allocation-free)
__device__ float g_s1val[ROWS][KTOP];
__device__ int   g_s1idx[ROWS][KTOP];
__device__ int   g_arrive[BSZ];   // zero-init; finisher resets -> graph-replay safe

__device__ __forceinline__ unsigned ford(float f) {
    unsigned u = __float_as_uint(f);
    return u ^ ((unsigned)((int)u >> 31) | 0x80000000u);
}
__device__ __forceinline__ float funord(unsigned u) {
    return __uint_as_float((u & 0x80000000u) ? (u ^ 0x80000000u) : ~u);
}
__device__ __forceinline__ u64 umax64(u64 a, u64 b) { return a > b ? a : b; }
__device__ __forceinline__ float vloadf(const float* p) { return *(const volatile float*)p; }
__device__ __forceinline__ int   vloadi(const int*   p) { return *(const volatile int*)p; }

// Exact block top-16 of THREADS candidates (0 = empty, nonzero keys unique).
// Winners descending in win[0..15]. All threads must call.
__device__ __forceinline__ void block_topk16_1(u64 loc0, u64* win, u64* wtmp,
                                               int tid, int lane, int wid) {
    u64 loc = loc0;
    for (int r = 0; r < KTOP; ++r) {
        u64 lm = loc;
        u64 wm = lm;
#pragma unroll
        for (int off = 16; off; off >>= 1)
            wm = umax64(wm, __shfl_down_sync(0xffffffffu, wm, off));
        wm = __shfl_sync(0xffffffffu, wm, 0);
        if (lane == 0) wtmp[wid * KTOP + r] = wm;
        if (lm == wm && wm) loc = 0ull;
    }
    __syncthreads();
    if (wid == 0) {
        u64 m[4];                 // 8 warps * 16 = 128 keys, 4 per lane
#pragma unroll
        for (int s = 0; s < 4; ++s) m[s] = wtmp[lane + s * 32];
        for (int r = 0; r < KTOP; ++r) {
            u64 lm = umax64(umax64(m[0], m[1]), umax64(m[2], m[3]));
            u64 wm = lm;
#pragma unroll
            for (int off = 16; off; off >>= 1)
                wm = umax64(wm, __shfl_down_sync(0xffffffffu, wm, off));
            wm = __shfl_sync(0xffffffffu, wm, 0);
            if (lane == 0) win[r] = wm;
            if (lm == wm && wm) {
#pragma unroll
                for (int s = 0; s < 4; ++s) if (m[s] == wm) m[s] = 0ull;
            }
        }
    }
    __syncthreads();
}

// Rare big-buffer selection: smem-scan, low register footprint by design.
// Zeroes winners inside buf.
__device__ __noinline__ void topk16_scan(u64* buf, int C, u64* win, u64* wtmp,
                                         int tid, int lane, int wid) {
    for (int r = 0; r < KTOP; ++r) {
        u64 lm = 0ull;
        for (int e = tid; e < C; e += THREADS) lm = umax64(lm, buf[e]);
#pragma unroll
        for (int off = 16; off; off >>= 1)
            lm = umax64(lm, __shfl_down_sync(0xffffffffu, lm, off));
        if (lane == 0) wtmp[wid] = lm;
        __syncthreads();
        if (tid == 0) {
            u64 w = wtmp[0];
#pragma unroll
            for (int s = 1; s < NWARP; ++s) w = umax64(w, wtmp[s]);
            win[r] = w;
        }
        __syncthreads();
        u64 w = win[r];
        for (int e = tid; e < C; e += THREADS)
            if (buf[e] == w) buf[e] = 0ull;    // unique keys -> one owner
        __syncthreads();
    }
}

__global__ __launch_bounds__(THREADS, 4)
void dss_kernel(const float* __restrict__ lprobs,
                const float* __restrict__ scores,
                const int* __restrict__ stepp, int sdim,
                float* __restrict__ out) {
    __shared__ u64 buf[CAP];
    __shared__ u64 win[KTOP];
    __shared__ u64 wtmp[NWARP * KTOP];
    __shared__ int cnt;
    __shared__ int lastflag;

    const int r    = blockIdx.x;
    const int b    = r / BEAM;
    const int tid  = threadIdx.x;
    const int lane = tid & 31;
    const int wid  = tid >> 5;

    int step = *stepp;
    if (step < 0 || step > sdim) step = sdim;
    const float add = (step > 0) ? scores[r * sdim + (step - 1)] : 0.0f;

    if (tid == 0) cnt = 0;

    const float* base = lprobs + (size_t)r * VOCAB;
    const uintptr_t addr = (uintptr_t)base;
    const int pre  = (int)(((16u - (unsigned)(addr & 15u)) & 15u) >> 2);  // 0..3
    const int NV4  = (VOCAB - pre) >> 2;
    const int tail = VOCAB - pre - (NV4 << 2);
    const float4* b4 = (const float4*)(base + pre);

    const int NITER = (NV4 + 2 * THREADS - 1) / (2 * THREADS);   // 25
    const int NFULL = NV4 >> 9;                                  // 24 full iters

    float T;
    float4 A0, A1, B0, B1;
    const float4 FILL = make_float4(NEG_INF, NEG_INF, NEG_INF, NEG_INF);

#define LD2(IT, R0, R1) do {                                   \
        int _i0 = (IT) * 2 * THREADS + tid;                    \
        int _i1 = _i0 + THREADS;                               \
        R0 = (_i0 < NV4) ? __ldcs(b4 + _i0) : FILL;            \
        R1 = (_i1 < NV4) ? __ldcs(b4 + _i1) : FILL;            \
    } while (0)

#define LD2U(IT, R0, R1) do {                                  \
        int _i0 = (IT) * 2 * THREADS + tid;                    \
        R0 = __ldcs(b4 + _i0);                                 \
        R1 = __ldcs(b4 + _i0 + THREADS);                       \
    } while (0)

    // gate on raw max + single add (fp add monotone); slow path: per-element
    // predicated atomic append with per-append CAP bounds check (overflow ->
    // cnt ends > CAP -> exact fallback pass; statistically never fires).
#define PROC(IT, R0, R1) do {                                                 \
        float m8 = fmaxf(fmaxf(fmaxf(R0.x, R0.y), fmaxf(R0.z, R0.w)),         \
                         fmaxf(fmaxf(R1.x, R1.y), fmaxf(R1.z, R1.w)));        \
        if (__any_sync(0xffffffffu, m8 + add >= T)) {                         \
            const int _i0 = (IT) * 2 * THREADS + tid;                         \
            float vv[8] = {R0.x + add, R0.y + add, R0.z + add, R0.w + add,    \
                           R1.x + add, R1.y + add, R1.z + add, R1.w + add};   \
            _Pragma("unroll")                                                 \
            for (int j = 0; j < 8; ++j) {                                     \
                if (vv[j] >= T) {                                             \
                    int p = atomicAdd(&cnt, 1);                               \
                    unsigned gidx = (unsigned)(pre +                          \
                        (_i0 + (j >> 2) * THREADS) * 4 + (j & 3));            \
                    if (p < CAP)                                              \
                        buf[p] = ((u64)ford(vv[j]) << 32) | (unsigned)~gidx;  \
                }                                                             \
            }                                                                 \
        }                                                                     \
    } while (0)

#define PROLOGUE() do {                                                       \
        if (tid < pre) {                                                      \
            float v = base[tid] + add;                                        \
            if (v >= T) {                                                     \
                int p = atomicAdd(&cnt, 1);                                   \
                if (p < CAP)                                                  \
                    buf[p] = ((u64)ford(v) << 32) | (unsigned)~((unsigned)tid);\
            }                                                                 \
        }                                                                     \
        int t2 = tid - 64;                                                    \
        if (t2 >= 0 && t2 < tail) {                                           \
            int gib = pre + (NV4 << 2) + t2;                                  \
            float v = base[gib] + add;                                        \
            if (v >= T) {                                                     \
                int p = atomicAdd(&cnt, 1);                                   \
                if (p < CAP)                                                  \
                    buf[p] = ((u64)ford(v) << 32) | (unsigned)~((unsigned)gib);\
            }                                                                 \
        }                                                                     \
    } while (0)

    // Fallback-only compaction: read-sync-branch (uniform).
#define COMPACT_IF(THRESH) do {                                               \
        __syncthreads();                                                      \
        int _Cg = cnt;                                                        \
        __syncthreads();                                                      \
        if (_Cg > (THRESH)) {                                                 \
            topk16_scan(buf, _Cg, win, wtmp, tid, lane, wid);                 \
            if (tid < KTOP) buf[tid] = win[tid];                              \
            if (tid == 0) cnt = KTOP;                                         \
            T = funord((unsigned)(win[KTOP - 1] >> 32));                      \
            __syncthreads();                                                  \
        }                                                                     \
    } while (0)

    // ---------- PASS 0: fixed statistical threshold, ZERO barriers ----------
    LD2U(0, A0, A1);
    LD2U(1, B0, B1);
    T = add + 3.1f;          // P(N(0,1) >= 3.1) ~ 9.7e-4 -> ~49 survivors expected
    __syncthreads();         // cnt = 0 visible
    PROLOGUE();

    int it = 0;
    for (; it + 3 < NFULL; it += 2) {        // loads it+2, it+3 all in-bounds
        PROC(it, A0, A1);
        LD2U(it + 2, A0, A1);
        PROC(it + 1, B0, B1);
        LD2U(it + 3, B0, B1);
    }
    PROC(it, A0, A1);
    LD2(NFULL, A0, A1);
    PROC(it + 1, B0, B1);
    if (NFULL < NITER) PROC(NFULL, A0, A1);

    __syncthreads();
    int Cend = cnt;
    __syncthreads();

    // ---------- FALLBACK (adversarial only): exact seed + compaction loop ------
    if (Cend < KTOP || Cend > CAP) {
        if (tid == 0) cnt = 0;
        LD2(0, A0, A1);
        {   // seed T = 16th of 256 per-thread maxima -> guarantees >=16 survivors
            float mx = fmaxf(fmaxf(fmaxf(A0.x, A0.y), fmaxf(A0.z, A0.w)),
                             fmaxf(fmaxf(A1.x, A1.y), fmaxf(A1.z, A1.w))) + add;
            block_topk16_1(((u64)ford(mx) << 32) | (unsigned)~((unsigned)tid),
                           win, wtmp, tid, lane, wid);   // also syncs cnt=0
            T = funord((unsigned)(win[KTOP - 1] >> 32));
        }
        PROLOGUE();
        for (int j2 = 0; j2 < NITER; ++j2) {
            LD2(j2, A0, A1);
            PROC(j2, A0, A1);
            COMPACT_IF(FHI);                 // bounded: cnt stays well under CAP
        }
        __syncthreads();
        Cend = cnt;
        __syncthreads();
    }

    // ---------- final exact selection for this row ----------
    if (Cend <= THREADS) {
        block_topk16_1((tid < Cend) ? buf[tid] : 0ull, win, wtmp, tid, lane, wid);
    } else {
        topk16_scan(buf, Cend, win, wtmp, tid, lane, wid);
    }

    if (tid < KTOP) {
        u64 w = win[tid];
        g_s1val[r][tid] = funord((unsigned)(w >> 32));
        g_s1idx[r][tid] = (int)~((unsigned)w);
    }
    __threadfence();
    __syncthreads();

    // last CTA per batch runs the final 128 -> 16 selection
    if (tid == 0) lastflag = (atomicAdd(&g_arrive[b], 1) == BEAM - 1) ? 1 : 0;
    __syncthreads();
    if (!lastflag) return;
    __threadfence();   // acquire: see all beams' g_s1 writes

    float* out_scores = out;
    float* out_idx    = out + BSZ * KTOP;
    float* out_beam   = out + 2 * BSZ * KTOP;

    if (step == 0) {
        if (tid < KTOP) {
            out_scores[b * KTOP + tid] = vloadf(&g_s1val[b * BEAM][tid]);
            out_idx[b * KTOP + tid]    = (float)vloadi(&g_s1idx[b * BEAM][tid]);
            out_beam[b * KTOP + tid]   = 0.0f;
        }
        if (tid == 0) g_arrive[b] = 0;
        return;
    }

    {
        u64 k = 0ull;
        if (tid < BEAM * KTOP) {
            const int beam = tid >> 4, pos = tid & 15;
            const float v = vloadf(&g_s1val[b * BEAM + beam][pos])
                            - (float)(pos + 1) * 0.5f;
            k = ((u64)ford(v) << 32) | (unsigned)~((unsigned)tid);
        }
        block_topk16_1(k, win, wtmp, tid, lane, wid);
    }
    if (tid < KTOP) {
        u64 w = win[tid];
        const int j = (int)~((unsigned)w);       // flat candidate == reference fi
        const int beam = j >> 4, pos = j & 15;
        out_scores[b * KTOP + tid] = funord((unsigned)(w >> 32));
        out_idx[b * KTOP + tid]    = (float)vloadi(&g_s1idx[b * BEAM + beam][pos]);
        out_beam[b * KTOP + tid]   = (float)beam;
    }
    if (tid == 0) g_arrive[b] = 0;
}

extern "C" void kernel_launch(void* const* d_in, const int* in_sizes, int n_in,
                              void* d_out, int out_size) {
    const float* lprobs = (const float*)d_in[0];
    const float* scores = (const float*)d_in[1];
    const int*   stepp  = (const int*)d_in[2];
    const int sdim = in_sizes[1] / ROWS;

    dss_kernel<<<ROWS, THREADS>>>(lprobs, scores, stepp, sdim, (float*)d_out);
}